// round 8
// baseline (speedup 1.0000x reference)
#include <cuda_runtime.h>
#include <cstdint>

// Gaussian 3D covariance: cov = (R*diag(exp(ls))) @ R^T per point.
// N=4M, HBM-streaming, plateaued ~36.5us kernel across 7 variants.
// R8: 256-bit memory ops (sm_103a ld/st.global.v8.f32), 2 adjacent
// points/thread, TPB=128 (PPB=256 divides N=4e6 exactly -> zero
// predication), smem-staged v8 flush. Halves LSU wavefronts and
// lengthens DRAM bursts.

constexpr int TPB = 128;
constexpr int PPB = 256;   // 2 points per thread, adjacent

__device__ __forceinline__ void ldg_v8(const float* p, float* v) {
    asm volatile("ld.global.nc.v8.f32 {%0,%1,%2,%3,%4,%5,%6,%7}, [%8];"
                 : "=f"(v[0]), "=f"(v[1]), "=f"(v[2]), "=f"(v[3]),
                   "=f"(v[4]), "=f"(v[5]), "=f"(v[6]), "=f"(v[7])
                 : "l"(p));
}
__device__ __forceinline__ void stg_v8(float* p, const float* v) {
    asm volatile("st.global.v8.f32 [%0], {%1,%2,%3,%4,%5,%6,%7,%8};"
                 :: "l"(p),
                    "f"(v[0]), "f"(v[1]), "f"(v[2]), "f"(v[3]),
                    "f"(v[4]), "f"(v[5]), "f"(v[6]), "f"(v[7])
                 : "memory");
}

__device__ __forceinline__ void compute_cov(
    float qw0, float qx0, float qy0, float qz0,
    float lsx, float lsy, float lsz,
    float* __restrict__ p)
{
    const float sx = __expf(lsx);
    const float sy = __expf(lsy);
    const float sz = __expf(lsz);

    const float d   = qw0 * qw0 + qx0 * qx0 + qy0 * qy0 + qz0 * qz0;
    const float inv = rsqrtf(fmaxf(d, 1e-24f));
    const float qw = qw0 * inv, qx = qx0 * inv, qy = qy0 * inv, qz = qz0 * inv;

    const float r00 = 1.f - 2.f * (qy * qy + qz * qz);
    const float r01 = 2.f * (qx * qy - qz * qw);
    const float r02 = 2.f * (qx * qz + qy * qw);
    const float r10 = 2.f * (qx * qy + qz * qw);
    const float r11 = 1.f - 2.f * (qx * qx + qz * qz);
    const float r12 = 2.f * (qy * qz - qx * qw);
    const float r20 = 2.f * (qx * qz - qy * qw);
    const float r21 = 2.f * (qy * qz + qx * qw);
    const float r22 = 1.f - 2.f * (qx * qx + qy * qy);

    const float a0 = r00 * sx, a1 = r01 * sy, a2 = r02 * sz;
    const float b0 = r10 * sx, b1 = r11 * sy, b2 = r12 * sz;
    const float c0 = r20 * sx, c1 = r21 * sy, c2 = r22 * sz;

    p[0] = a0 * r00 + a1 * r01 + a2 * r02;
    p[1] = a0 * r10 + a1 * r11 + a2 * r12;
    p[2] = a0 * r20 + a1 * r21 + a2 * r22;
    p[3] = b0 * r00 + b1 * r01 + b2 * r02;
    p[4] = b0 * r10 + b1 * r11 + b2 * r12;
    p[5] = b0 * r20 + b1 * r21 + b2 * r22;
    p[6] = c0 * r00 + c1 * r01 + c2 * r02;
    p[7] = c0 * r10 + c1 * r11 + c2 * r12;
    p[8] = c0 * r20 + c1 * r21 + c2 * r22;
}

__global__ __launch_bounds__(TPB) void cov_kernel(
    const float* __restrict__ quat,    // [n*4] (w,x,y,z)
    const float* __restrict__ ls,      // [n*3]
    float*       __restrict__ out)     // [n*9]
{
    __shared__ __align__(32) float sbuf[PPB * 9];   // 9216 B

    const int t    = threadIdx.x;
    const int base = blockIdx.x * PPB;
    const int p0   = base + 2 * t;                  // even -> 32B-aligned quat

    // Two adjacent quaternions in one 256-bit load.
    float q[8];
    ldg_v8(&quat[4 * p0], q);

    // Six log-scales for the pair as three float2 loads (8B-aligned).
    const float2* lp = reinterpret_cast<const float2*>(&ls[3 * p0]);
    const float2 A = __ldcs(&lp[0]);
    const float2 B = __ldcs(&lp[1]);
    const float2 C = __ldcs(&lp[2]);

    compute_cov(q[0], q[1], q[2], q[3], A.x, A.y, B.x, &sbuf[t * 18]);
    compute_cov(q[4], q[5], q[6], q[7], B.y, C.x, C.y, &sbuf[t * 18 + 9]);
    __syncthreads();

    // Flush 2304 floats = 288 x 256-bit stores (out base 9216B-aligned).
    float* g = out + (long long)base * 9;
    #pragma unroll
    for (int j = t; j < PPB * 9 / 8; j += TPB) {
        float v[8];
        const float4 lo = *reinterpret_cast<const float4*>(&sbuf[8 * j]);
        const float4 hi = *reinterpret_cast<const float4*>(&sbuf[8 * j + 4]);
        v[0] = lo.x; v[1] = lo.y; v[2] = lo.z; v[3] = lo.w;
        v[4] = hi.x; v[5] = hi.y; v[6] = hi.z; v[7] = hi.w;
        stg_v8(&g[8 * j], v);
    }
}

extern "C" void kernel_launch(void* const* d_in, const int* in_sizes, int n_in,
                              void* d_out, int out_size) {
    const float* quat = (const float*)d_in[0];  // [N,4] float32
    const float* ls   = (const float*)d_in[1];  // [N,3] float32
    float*       out  = (float*)d_out;          // [N,3,3] float32

    const int n = in_sizes[0] / 4;              // 4,000,000
    const int blocks = (n + PPB - 1) / PPB;     // 15625 exact for N=4e6
    cov_kernel<<<blocks, TPB>>>(quat, ls, out);
}

// round 9
// speedup vs baseline: 1.0378x; 1.0378x over previous
#include <cuda_runtime.h>

// Gaussian 3D covariance: cov = (R*diag(exp(ls))) @ R^T per point.
// N=4M, pure HBM streaming. After 8 structural variants (2pt/thread, TMA
// bulk store, L2 evict policies, .cs hints, persistent grid, v8.f32 ops)
// the kernel is pinned at ~36.5us / ~5.4TB/s mixed-stream DRAM ceiling.
// R9 = the empirically best config (R1: default cache ops, TPB=256,
// smem-staged float4 flush) with tail paths removed (256 | N exactly).

constexpr int TPB = 256;

__global__ __launch_bounds__(TPB) void cov_kernel(
    const float4* __restrict__ quat,   // [n] as float4 (w,x,y,z)
    const float*  __restrict__ ls,     // [n*3]
    float*        __restrict__ out)    // [n*9]
{
    __shared__ __align__(16) float sbuf[TPB * 9];

    const int i = blockIdx.x * TPB + threadIdx.x;

    const float4 q4 = quat[i];
    const float sx = __expf(ls[3 * i + 0]);
    const float sy = __expf(ls[3 * i + 1]);
    const float sz = __expf(ls[3 * i + 2]);

    const float d   = q4.x * q4.x + q4.y * q4.y + q4.z * q4.z + q4.w * q4.w;
    const float inv = rsqrtf(fmaxf(d, 1e-24f));
    const float qw = q4.x * inv;
    const float qx = q4.y * inv;
    const float qy = q4.z * inv;
    const float qz = q4.w * inv;

    const float r00 = 1.f - 2.f * (qy * qy + qz * qz);
    const float r01 = 2.f * (qx * qy - qz * qw);
    const float r02 = 2.f * (qx * qz + qy * qw);
    const float r10 = 2.f * (qx * qy + qz * qw);
    const float r11 = 1.f - 2.f * (qx * qx + qz * qz);
    const float r12 = 2.f * (qy * qz - qx * qw);
    const float r20 = 2.f * (qx * qz - qy * qw);
    const float r21 = 2.f * (qy * qz + qx * qw);
    const float r22 = 1.f - 2.f * (qx * qx + qy * qy);

    const float a0 = r00 * sx, a1 = r01 * sy, a2 = r02 * sz;
    const float b0 = r10 * sx, b1 = r11 * sy, b2 = r12 * sz;
    const float c0 = r20 * sx, c1 = r21 * sy, c2 = r22 * sz;

    float* p = &sbuf[threadIdx.x * 9];
    p[0] = a0 * r00 + a1 * r01 + a2 * r02;
    p[1] = a0 * r10 + a1 * r11 + a2 * r12;
    p[2] = a0 * r20 + a1 * r21 + a2 * r22;
    p[3] = b0 * r00 + b1 * r01 + b2 * r02;
    p[4] = b0 * r10 + b1 * r11 + b2 * r12;
    p[5] = b0 * r20 + b1 * r21 + b2 * r22;
    p[6] = c0 * r00 + c1 * r01 + c2 * r02;
    p[7] = c0 * r10 + c1 * r11 + c2 * r12;
    p[8] = c0 * r20 + c1 * r21 + c2 * r22;

    __syncthreads();

    // Coalesced full-block flush: 2304 floats = 576 float4s, default policy.
    float4*       o4 = reinterpret_cast<float4*>(out + (long long)blockIdx.x * (TPB * 9));
    const float4* s4 = reinterpret_cast<const float4*>(sbuf);
    #pragma unroll
    for (int j = threadIdx.x; j < TPB * 9 / 4; j += TPB)
        o4[j] = s4[j];
}

extern "C" void kernel_launch(void* const* d_in, const int* in_sizes, int n_in,
                              void* d_out, int out_size) {
    const float4* quat = (const float4*)d_in[0];  // [N,4] float32
    const float*  ls   = (const float*)d_in[1];   // [N,3] float32
    float*        out  = (float*)d_out;           // [N,3,3] float32

    const int n = in_sizes[0] / 4;                // 4,000,000 (divisible by 256)
    cov_kernel<<<n / TPB, TPB>>>(quat, ls, out);
}